// round 17
// baseline (speedup 1.0000x reference)
#include <cuda_runtime.h>

#define BB   1024
#define TT   512
#define IN   6
#define HH   64
#define GG   256
#define RR   8
#define NTH  512
#define NCTA (BB / RR)

// smem offsets (floats)
#define OFF_WHH0 0            // pair layout: W2[(kp*GG+g)*2 + (k&1)], 16384
#define OFF_WIH1 16384        // 16384
#define OFF_WHH1 32768        // 16384
#define OFF_WX   49152        // Wih0 (pair) 1536
#define OFF_B0   50688        // 256
#define OFF_B1   50944        // 256
#define OFF_GSH1 51200        // 2048  [g][r]
#define OFF_GSHP 53248        // 2048
#define OFF_HT0  55296        // 2 bufs x 512
#define OFF_HT1  56320        // 2 bufs x 512
#define OFF_XT   57344        // 2 bufs x 128
#define SMEM_FLOATS 57600
#define SMEM_BYTES  (SMEM_FLOATS * 4)   // 230400

typedef unsigned long long u64;

__device__ __forceinline__ u64 ffma2(u64 a, u64 b, u64 c) {
    u64 d;
    asm("fma.rn.f32x2 %0, %1, %2, %3;" : "=l"(d) : "l"(a), "l"(b), "l"(c));
    return d;
}
__device__ __forceinline__ float hsum2(u64 a) {
    union { u64 u; float2 f; } cvt; cvt.u = a;
    return cvt.f.x + cvt.f.y;
}
__device__ __forceinline__ float tanhf_(float x) {
    float y; asm("tanh.approx.f32 %0, %1;" : "=f"(y) : "f"(x)); return y;
}
__device__ __forceinline__ float sigmoidf_(float x) {
    return fmaf(0.5f, tanhf_(0.5f * x), 0.5f);
}
// h slot for k-pair p: pairs p, p+8, p+16, p+24 land in consecutive 64B slots
__device__ __forceinline__ int hslot(int p) {
    return (p & 7) * 4 + (p >> 3);
}

__global__ void __launch_bounds__(NTH, 1)
lstm_net_kernel(const float* __restrict__ x,
                const float* __restrict__ Wih0, const float* __restrict__ Whh0,
                const float* __restrict__ bih0, const float* __restrict__ bhh0,
                const float* __restrict__ Wih1, const float* __restrict__ Whh1,
                const float* __restrict__ bih1, const float* __restrict__ bhh1,
                const float* __restrict__ Wfc1, const float* __restrict__ bfc1,
                const float* __restrict__ Wfc2, const float* __restrict__ bfc2,
                float* __restrict__ out) {
    extern __shared__ float s[];
    float* Whh0s = s + OFF_WHH0;
    float* Wih1s = s + OFF_WIH1;
    float* Whh1s = s + OFF_WHH1;
    float* WXs   = s + OFF_WX;
    float* b0s   = s + OFF_B0;
    float* b1s   = s + OFF_B1;
    float* gsh1  = s + OFF_GSH1;
    float* gshP  = s + OFF_GSHP;
    float* hT0   = s + OFF_HT0;
    float* hT1   = s + OFF_HT1;
    float* xT    = s + OFF_XT;

    const int tid  = threadIdx.x;
    const int lane = tid & 31;
    const int w    = tid >> 5;
    const int kq   = lane & 3;          // k-quarter: pairs kq*8 .. kq*8+7
    const int m    = w * 8 + (lane >> 2); // col-pair index 0..127
    const int g0   = 2 * m;             // this thread's two gate columns: g0, g0+1
    const int b0_  = blockIdx.x * RR;

    // ---- Stage weights (pair layout) ----
    for (int i = tid; i < HH * GG; i += NTH) {
        int gg_ = i >> 6;
        int k   = i & 63;
        int dp  = ((k >> 1) * GG + gg_) * 2 + (k & 1);
        Whh0s[dp] = Whh0[i];
        Wih1s[dp] = Wih1[i];
        Whh1s[dp] = Whh1[i];
    }
    for (int i = tid; i < IN * GG; i += NTH) {
        int gg_ = i / IN;
        int k   = i - gg_ * IN;
        WXs[((k >> 1) * GG + gg_) * 2 + (k & 1)] = Wih0[i];
    }
    if (tid < GG) {
        b0s[tid] = bih0[tid] + bhh0[tid];
        b1s[tid] = bih1[tid] + bhh1[tid];
    }
    for (int i = tid; i < 2048; i += NTH) hT0[i] = 0.0f;   // zeros hT0+hT1

    // x staging role (tid < 48)
    const int xk = tid >> 3;
    const int xr = tid & 7;
    const bool isx = (tid < 48);
    const float* xgp = x + (size_t)(b0_ + xr) * TT * IN + xk;
    float* xslot0 = xT + (xk >> 1) * 16 + xr * 2 + (xk & 1);
    float xreg = 0.0f;
    if (isx) xreg = xgp[0];                           // x_0

    // update role
    const int uj = tid >> 3;      // 0..63
    const int ur = tid & 7;       // 0..7
    const int hix = hslot(uj >> 1) * 16 + ur * 2 + (uj & 1);
    float c0 = 0.0f, c1 = 0.0f;

    __syncthreads();

    // ---- per-lane store target: kq0->set1 col0, kq1->set1 col1, kq2->setP col0, kq3->setP col1
    const int colS = g0 + (kq & 1);
    const float bstore = (kq >> 1) ? b0s[colS] : b1s[colS];
    float* gstp = ((kq >> 1) ? gshP : gsh1) + colS * 8;

    // ---- hoisted pointers ----
    const float* pw1 = Wih1s + ((kq * 8) * GG + g0) * 2;   // + i*512 (floats)
    const float* pwP = Whh0s + ((kq * 8) * GG + g0) * 2;
    const float* pwH = Whh1s + ((kq * 8) * GG + g0) * 2;
    const float* pwX = WXs + ((kq < 3 ? kq : 0) * GG + g0) * 2;
    const char* ph0 = (const char*)(hT0 + kq * 16);        // + rbB, + i*256B
    const char* ph1 = (const char*)(hT1 + kq * 16);
    const char* pxq = (const char*)(xT + kq * 16);         // + (rbB>>2)
    const float* g1u = gsh1 + uj * 8 + ur;
    const float* gPu = gshP + uj * 8 + ur;
    char* ph1w = (char*)(hT1 + hix);
    char* ph0w = (char*)(hT0 + hix);
    char* pxw  = (char*)xslot0;

    // publish x_0 into xT buf1 (scratch, +128 floats)
    if (isx) xslot0[128] = xreg;
    __syncthreads();

#define FMA8(ACC, W, A, B, C, D)                        \
    ACC[0] = ffma2(A.x, W, ACC[0]);                      \
    ACC[1] = ffma2(A.y, W, ACC[1]);                      \
    ACC[2] = ffma2(B.x, W, ACC[2]);                      \
    ACC[3] = ffma2(B.y, W, ACC[3]);                      \
    ACC[4] = ffma2(C.x, W, ACC[4]);                      \
    ACC[5] = ffma2(C.y, W, ACC[5]);                      \
    ACC[6] = ffma2(D.x, W, ACC[6]);                      \
    ACC[7] = ffma2(D.y, W, ACC[7]);

    // reduce+store: v0..v3 partials over kq -> lane kq owns its array, stores it
#define REDUCE_STORE(V0, V1, V2, V3)                                        \
    {                                                                        \
        float va[8], uA[8], uB[8];                                           \
        _Pragma("unroll")                                                    \
        for (int j = 0; j < 8; j++) {                                        \
            float t0 = (kq < 2) ? V2[j] : V0[j];                             \
            float r0 = __shfl_xor_sync(0xffffffffu, t0, 2);                  \
            uA[j] = ((kq < 2) ? V0[j] : V2[j]) + r0;                         \
            float t1 = (kq < 2) ? V3[j] : V1[j];                             \
            float r1_ = __shfl_xor_sync(0xffffffffu, t1, 2);                 \
            uB[j] = ((kq < 2) ? V1[j] : V3[j]) + r1_;                        \
        }                                                                    \
        _Pragma("unroll")                                                    \
        for (int j = 0; j < 8; j++) {                                        \
            float t = (kq & 1) ? uA[j] : uB[j];                              \
            float r = __shfl_xor_sync(0xffffffffu, t, 1);                    \
            va[j] = ((kq & 1) ? uB[j] : uA[j]) + r;                          \
        }                                                                    \
        *(float4*)(gstp) = make_float4(va[0] + bstore, va[1] + bstore,       \
                                       va[2] + bstore, va[3] + bstore);      \
        *(float4*)(gstp + 4) = make_float4(va[4] + bstore, va[5] + bstore,   \
                                           va[6] + bstore, va[7] + bstore);  \
    }

    // ================= PROLOGUE: gates0_0 = bias0 + Wih0 @ x_0 =================
    {
        u64 a2[8] = {0,0,0,0,0,0,0,0};     // setP col0
        u64 a3[8] = {0,0,0,0,0,0,0,0};     // setP col1
        if (kq < 3) {
            const float* xp = (const float*)(pxq) + 128;   // buf1
            ulonglong2 A = ((const ulonglong2*)xp)[0];
            ulonglong2 B = ((const ulonglong2*)xp)[1];
            ulonglong2 C = ((const ulonglong2*)xp)[2];
            ulonglong2 D = ((const ulonglong2*)xp)[3];
            ulonglong2 wx = *(const ulonglong2*)(pwX);
            FMA8(a2, wx.x, A, B, C, D)
            FMA8(a3, wx.y, A, B, C, D)
        }
        float v0[8], v1[8], v2[8], v3[8];
#pragma unroll
        for (int j = 0; j < 8; j++) {
            v0[j] = 0.0f; v1[j] = 0.0f;
            v2[j] = hsum2(a2[j]); v3[j] = hsum2(a3[j]);
        }
        REDUCE_STORE(v0, v1, v2, v3)
        if (isx) xreg = xgp[1 * IN];   // x_1
        __syncthreads();

        // prologue update: layer 0 only -> h0_0 (buf 0)
        float gi = sigmoidf_(gPu[0]);
        float gf = sigmoidf_(gPu[64 * 8]);
        float gc = tanhf_  (gPu[128 * 8]);
        float go = sigmoidf_(gPu[192 * 8]);
        c0 = fmaf(gf, c0, gi * gc);
        hT0[hix] = go * tanhf_(c0);
        if (isx) xslot0[0] = xreg;     // buf 0
        __syncthreads();
    }

    // ================= MAIN LOOP =================
    int rbB = 0;                 // read-buffer byte offset (h bufs: 0/2048)
    for (int t = 0; t < TT; t++) {
        const int wbB = rbB ^ 2048;

        if (isx && t + 2 < TT)
            xreg = xgp[(size_t)(t + 2) * IN];

        u64 a0[8] = {0,0,0,0,0,0,0,0};   // set1 col0
        u64 a1[8] = {0,0,0,0,0,0,0,0};   // set1 col1
        u64 a2[8] = {0,0,0,0,0,0,0,0};   // setP col0
        u64 a3[8] = {0,0,0,0,0,0,0,0};   // setP col1

        const float* h0b = (const float*)(ph0 + rbB);
        const float* h1b = (const float*)(ph1 + rbB);
#pragma unroll
        for (int i = 0; i < 8; i++) {
            ulonglong2 wq1 = *(const ulonglong2*)(pw1 + i * 512);
            ulonglong2 wqP = *(const ulonglong2*)(pwP + i * 512);
            ulonglong2 wqH = *(const ulonglong2*)(pwH + i * 512);

            const float* p0 = h0b + i * 64;
            ulonglong2 A = ((const ulonglong2*)p0)[0];
            ulonglong2 B = ((const ulonglong2*)p0)[1];
            ulonglong2 C = ((const ulonglong2*)p0)[2];
            ulonglong2 D = ((const ulonglong2*)p0)[3];
            FMA8(a0, wq1.x, A, B, C, D)
            FMA8(a1, wq1.y, A, B, C, D)
            FMA8(a2, wqP.x, A, B, C, D)
            FMA8(a3, wqP.y, A, B, C, D)

            const float* p1 = h1b + i * 64;
            ulonglong2 E = ((const ulonglong2*)p1)[0];
            ulonglong2 F = ((const ulonglong2*)p1)[1];
            ulonglong2 Gq = ((const ulonglong2*)p1)[2];
            ulonglong2 Hq = ((const ulonglong2*)p1)[3];
            FMA8(a0, wqH.x, E, F, Gq, Hq)
            FMA8(a1, wqH.y, E, F, Gq, Hq)
        }
        // x part: lane kq handles x-pair kq (kq<3): accP += Wih0 @ x_{t+1}
        if (kq < 3) {
            const float* xp = (const float*)(pxq + (rbB >> 2));
            ulonglong2 A = ((const ulonglong2*)xp)[0];
            ulonglong2 B = ((const ulonglong2*)xp)[1];
            ulonglong2 C = ((const ulonglong2*)xp)[2];
            ulonglong2 D = ((const ulonglong2*)xp)[3];
            ulonglong2 wx = *(const ulonglong2*)(pwX);
            FMA8(a2, wx.x, A, B, C, D)
            FMA8(a3, wx.y, A, B, C, D)
        }

        // combine across k-quarters and store gates
        float v0[8], v1[8], v2[8], v3[8];
#pragma unroll
        for (int j = 0; j < 8; j++) {
            v0[j] = hsum2(a0[j]); v1[j] = hsum2(a1[j]);
            v2[j] = hsum2(a2[j]); v3[j] = hsum2(a3[j]);
        }
        REDUCE_STORE(v0, v1, v2, v3)
        __syncthreads();

        // ---------- PHASE 2: both cell updates ----------
        {
            float gi = sigmoidf_(g1u[0]);
            float gf = sigmoidf_(g1u[64 * 8]);
            float gc = tanhf_  (g1u[128 * 8]);
            float go = sigmoidf_(g1u[192 * 8]);
            c1 = fmaf(gf, c1, gi * gc);
            *(float*)(ph1w + wbB) = go * tanhf_(c1);          // h1_t
        }
        {
            float gi = sigmoidf_(gPu[0]);
            float gf = sigmoidf_(gPu[64 * 8]);
            float gc = tanhf_  (gPu[128 * 8]);
            float go = sigmoidf_(gPu[192 * 8]);
            c0 = fmaf(gf, c0, gi * gc);
            *(float*)(ph0w + wbB) = go * tanhf_(c0);          // h0_{t+1}
        }
        if (isx && t + 2 < TT)
            *(float*)(pxw + (wbB >> 2)) = xreg;               // x_{t+2}
        __syncthreads();

        rbB = wbB;
    }

    // ================= FC head: h1_{TT-1} lives in buffer TT&1 = 0 =================
    if (tid < 256) {
        const int row = tid >> 5;
        const int mm  = tid & 31;
        float acc2 = bfc1[mm];
#pragma unroll 8
        for (int k = 0; k < HH; k++) {
            int p = k >> 1;
            float hv = hT1[(TT & 1) * 512 + hslot(p) * 16 + row * 2 + (k & 1)];
            acc2 = fmaf(hv, Wfc1[mm * HH + k], acc2);
        }
        acc2 = fmaxf(acc2, 0.0f) * Wfc2[mm];
#pragma unroll
        for (int off = 16; off > 0; off >>= 1)
            acc2 += __shfl_down_sync(0xffffffffu, acc2, off);
        if (mm == 0)
            out[b0_ + row] = acc2 + bfc2[0];
    }
}

extern "C" void kernel_launch(void* const* d_in, const int* in_sizes, int n_in,
                              void* d_out, int out_size) {
    const float* x    = (const float*)d_in[0];
    const float* Wih0 = (const float*)d_in[1];
    const float* Whh0 = (const float*)d_in[2];
    const float* bih0 = (const float*)d_in[3];
    const float* bhh0 = (const float*)d_in[4];
    const float* Wih1 = (const float*)d_in[5];
    const float* Whh1 = (const float*)d_in[6];
    const float* bih1 = (const float*)d_in[7];
    const float* bhh1 = (const float*)d_in[8];
    const float* Wfc1 = (const float*)d_in[9];
    const float* bfc1 = (const float*)d_in[10];
    const float* Wfc2 = (const float*)d_in[11];
    const float* bfc2 = (const float*)d_in[12];
    float* out = (float*)d_out;

    cudaFuncSetAttribute(lstm_net_kernel,
                         cudaFuncAttributeMaxDynamicSharedMemorySize, SMEM_BYTES);
    lstm_net_kernel<<<NCTA, NTH, SMEM_BYTES>>>(
        x, Wih0, Whh0, bih0, bhh0, Wih1, Whh1, bih1, bhh1,
        Wfc1, bfc1, Wfc2, bfc2, out);
}